// round 1
// baseline (speedup 1.0000x reference)
#include <cuda_runtime.h>
#include <cuda_bf16.h>

// Scratch: segment start offsets, start[t] = first char index belonging to
// segment >= t. Size T+1 so start[t+1] is the exclusive end.
#define MAX_T_ (1 << 17)
__device__ int g_start[MAX_T_ + 1];

// Kernel 1: exploit sorted segment_ids — wherever the id changes between
// consecutive chars, fill start[] for every segment id in the gap (this also
// handles empty segments). Thread-per-char, fully coalesced.
__global__ void seg_starts_kernel(const int* __restrict__ seg, int N, int T) {
    int i = blockIdx.x * blockDim.x + threadIdx.x;
    if (i >= N) return;
    int cur  = seg[i];
    int prev = (i == 0) ? -1 : seg[i - 1];
    for (int t = prev + 1; t <= cur; ++t) g_start[t] = i;
    if (i == N - 1) {
        for (int t = cur + 1; t <= T; ++t) g_start[t] = N;
    }
}

// Kernel 2: warp-per-segment segment mean via vocab histogram.
//   - each lane holds emb[v][lane*4 .. lane*4+3] in registers (14 x float4,
//     statically indexed -> no local memory)
//   - vocab counts via ballot+popc over the segment's chars (uniform warp loop)
//   - result = (count[v]/len) dot emb[v], stored as one coalesced float4
__global__ void seg_mean_kernel(const float* __restrict__ emb,
                                const int* __restrict__ cidx,
                                float* __restrict__ out, int T) {
    int warp = threadIdx.x >> 5;
    int lane = threadIdx.x & 31;
    int t = blockIdx.x * (blockDim.x >> 5) + warp;
    if (t >= T) return;

    // Per-lane slice of the 14x128 embedding table (L1-resident after warmup).
    float4 ev[14];
#pragma unroll
    for (int v = 0; v < 14; ++v)
        ev[v] = *reinterpret_cast<const float4*>(emb + v * 128 + lane * 4);

    int s = g_start[t];
    int e = g_start[t + 1];

    int cnt[14];
#pragma unroll
    for (int v = 0; v < 14; ++v) cnt[v] = 0;

    // Loop bounds are warp-uniform (s, e identical across lanes), so
    // ballot_sync with the full mask is safe.
    for (int base = s; base < e; base += 32) {
        int i   = base + lane;
        int idx = (i < e) ? cidx[i] : -1;
#pragma unroll
        for (int v = 0; v < 14; ++v)
            cnt[v] += __popc(__ballot_sync(0xffffffffu, idx == v));
    }

    float scale = 1.0f / (float)max(e - s, 1);   // empty segment -> 0 output
    float4 a = make_float4(0.f, 0.f, 0.f, 0.f);
#pragma unroll
    for (int v = 0; v < 14; ++v) {
        float c = (float)cnt[v] * scale;
        a.x += c * ev[v].x;
        a.y += c * ev[v].y;
        a.z += c * ev[v].z;
        a.w += c * ev[v].w;
    }
    reinterpret_cast<float4*>(out)[t * 32 + lane] = a;
}

extern "C" void kernel_launch(void* const* d_in, const int* in_sizes, int n_in,
                              void* d_out, int out_size) {
    const float* char_emb     = (const float*)d_in[0];
    const int*   char_indices = (const int*)d_in[1];
    const int*   segment_ids  = (const int*)d_in[2];
    float*       out          = (float*)d_out;

    int N = in_sizes[1];           // total chars
    int T = out_size / 128;        // segments (d_model = 128)

    {
        int threads = 256;
        int blocks  = (N + threads - 1) / threads;
        seg_starts_kernel<<<blocks, threads>>>(segment_ids, N, T);
    }
    {
        int threads = 256;                     // 8 warps = 8 segments / block
        int segs_per_block = threads / 32;
        int blocks = (T + segs_per_block - 1) / segs_per_block;
        seg_mean_kernel<<<blocks, threads>>>(char_emb, char_indices, out, T);
    }
}

// round 2
// speedup vs baseline: 1.6608x; 1.6608x over previous
#include <cuda_runtime.h>
#include <cuda_bf16.h>

// Scratch: per-segment vocab histogram, f32, padded to 16 slots (64B) per
// segment. Slots 14,15 are never written -> stay zero after zero_hist.
#define MAX_T_ (1 << 17)
__device__ float g_hist[MAX_T_ * 16];

// ---------------------------------------------------------------------------
// Kernel 0: zero the histogram (8 MB), vectorized.
__global__ void zero_hist_kernel(int nvec4) {
    int i = blockIdx.x * blockDim.x + threadIdx.x;
    if (i < nvec4)
        reinterpret_cast<float4*>(g_hist)[i] = make_float4(0.f, 0.f, 0.f, 0.f);
}

// ---------------------------------------------------------------------------
// Kernel 1: thread-per-char histogram via f32 reduction-atomics (RED.ADD).
// Addresses are spread (avg multiplicity per bin < 1), so no contention issue.
__global__ void hist_kernel(const int* __restrict__ seg,
                            const int* __restrict__ cidx, int N) {
    int i = blockIdx.x * blockDim.x + threadIdx.x;
    if (i >= N) return;
    atomicAdd(&g_hist[(seg[i] << 4) + cidx[i]], 1.0f);
}

// ---------------------------------------------------------------------------
// Kernel 2: warp-per-segment 14x128 matvec:  out[t] = (hist[t]/len) @ emb.
// emb staged in shared memory; inner product uses packed f32x2 FMAs.
#define SEGS_PER_WARP 8

static __device__ __forceinline__ unsigned smem_addr_u32(const void* p) {
    unsigned r;
    asm("{ .reg .u64 t; cvta.to.shared.u64 t, %1; cvt.u32.u64 %0, t; }"
        : "=r"(r) : "l"(p));
    return r;
}

__global__ void matvec_kernel(const float* __restrict__ emb,
                              float* __restrict__ out, int T) {
    __shared__ float4 semb4[14 * 32];   // 14 vocab rows x 128 floats (7 KB)

    // Stage embedding table (full block cooperates; 448 float4 loads).
    for (int i = threadIdx.x; i < 14 * 32; i += blockDim.x)
        semb4[i] = reinterpret_cast<const float4*>(emb)[i];
    __syncthreads();

    const unsigned semb_base = smem_addr_u32(semb4);
    const int lane = threadIdx.x & 31;
    const int warp = threadIdx.x >> 5;
    const int warps_per_block = blockDim.x >> 5;
    const int t0 = (blockIdx.x * warps_per_block + warp) * SEGS_PER_WARP;

    for (int s = 0; s < SEGS_PER_WARP; ++s) {
        const int t = t0 + s;
        if (t >= T) return;

        // Broadcast-load this segment's 16 count slots (last 2 are zero).
        const float4* cw = reinterpret_cast<const float4*>(g_hist + (t << 4));
        float4 c0 = cw[0], c1 = cw[1], c2 = cw[2], c3 = cw[3];

        float len = ((c0.x + c0.y) + (c0.z + c0.w))
                  + ((c1.x + c1.y) + (c1.z + c1.w))
                  + ((c2.x + c2.y) + (c2.z + c2.w))
                  + (c3.x + c3.y);
        float scale = 1.0f / fmaxf(len, 1.0f);   // empty segment -> 0 output

        float cv[14];
        cv[0]  = c0.x * scale;  cv[1]  = c0.y * scale;
        cv[2]  = c0.z * scale;  cv[3]  = c0.w * scale;
        cv[4]  = c1.x * scale;  cv[5]  = c1.y * scale;
        cv[6]  = c1.z * scale;  cv[7]  = c1.w * scale;
        cv[8]  = c2.x * scale;  cv[9]  = c2.y * scale;
        cv[10] = c2.z * scale;  cv[11] = c2.w * scale;
        cv[12] = c3.x * scale;  cv[13] = c3.y * scale;

        // Accumulate 4 output floats per lane as 2 packed f32x2 registers.
        unsigned long long a01 = 0ull, a23 = 0ull;
        const unsigned lane_off = semb_base + (unsigned)(lane * 16);
#pragma unroll
        for (int v = 0; v < 14; ++v) {
            unsigned long long e01, e23, cc;
            unsigned addr = lane_off + (unsigned)(v * 512);
            asm("ld.shared.v2.u64 {%0, %1}, [%2];"
                : "=l"(e01), "=l"(e23) : "r"(addr));
            unsigned cb = __float_as_uint(cv[v]);
            asm("mov.b64 %0, {%1, %1};" : "=l"(cc) : "r"(cb));
            asm("fma.rn.f32x2 %0, %1, %2, %0;" : "+l"(a01) : "l"(cc), "l"(e01));
            asm("fma.rn.f32x2 %0, %1, %2, %0;" : "+l"(a23) : "l"(cc), "l"(e23));
        }

        float4 r;
        asm("mov.b64 {%0, %1}, %2;" : "=f"(r.x), "=f"(r.y) : "l"(a01));
        asm("mov.b64 {%0, %1}, %2;" : "=f"(r.z), "=f"(r.w) : "l"(a23));
        reinterpret_cast<float4*>(out)[t * 32 + lane] = r;
    }
}

// ---------------------------------------------------------------------------
extern "C" void kernel_launch(void* const* d_in, const int* in_sizes, int n_in,
                              void* d_out, int out_size) {
    const float* char_emb     = (const float*)d_in[0];
    const int*   char_indices = (const int*)d_in[1];
    const int*   segment_ids  = (const int*)d_in[2];
    float*       out          = (float*)d_out;

    int N = in_sizes[1];          // total chars
    int T = out_size / 128;       // segments (d_model = 128)

    {   // zero histogram: T*16 floats = T*4 float4
        int nvec4 = T * 4;
        int threads = 256;
        zero_hist_kernel<<<(nvec4 + threads - 1) / threads, threads>>>(nvec4);
    }
    {   // histogram
        int threads = 256;
        hist_kernel<<<(N + threads - 1) / threads, threads>>>(segment_ids,
                                                              char_indices, N);
    }
    {   // matvec: 8 warps/block, 8 segments/warp -> 64 segments/block
        int threads = 256;
        int segs_per_block = (threads / 32) * SEGS_PER_WARP;
        int blocks = (T + segs_per_block - 1) / segs_per_block;
        matvec_kernel<<<blocks, threads>>>(char_emb, out, T);
    }
}

// round 3
// speedup vs baseline: 2.3216x; 1.3979x over previous
#include <cuda_runtime.h>
#include <cuda_bf16.h>

// Per-segment vocab histogram, f32, 16 slots (64B) per segment.
// Slots 14,15 never written. Zero-initialized at module load; matvec re-zeros
// after consuming, so every graph replay starts from zeros.
#define MAX_T_ (1 << 17)
__device__ float g_hist[MAX_T_ * 16];

// ---------------------------------------------------------------------------
// Kernel 1: histogram, 4 chars per thread via int4 loads, f32 RED.ADD.
__global__ void hist_kernel(const int4* __restrict__ seg4,
                            const int4* __restrict__ cidx4,
                            const int* __restrict__ seg,
                            const int* __restrict__ cidx,
                            int nq, int N) {
    int i = blockIdx.x * blockDim.x + threadIdx.x;
    if (i < nq) {
        int4 s = seg4[i];
        int4 c = cidx4[i];
        atomicAdd(&g_hist[(s.x << 4) + c.x], 1.0f);
        atomicAdd(&g_hist[(s.y << 4) + c.y], 1.0f);
        atomicAdd(&g_hist[(s.z << 4) + c.z], 1.0f);
        atomicAdd(&g_hist[(s.w << 4) + c.w], 1.0f);
    } else if (i == nq) {            // tail (N not multiple of 4)
        for (int j = nq * 4; j < N; ++j)
            atomicAdd(&g_hist[(seg[j] << 4) + cidx[j]], 1.0f);
    }
}

// ---------------------------------------------------------------------------
// Kernel 2: warp-per-8-segments matvec  out[t] = (hist[t] @ emb) / len,
// emb table register-resident, f32x2 packed FMAs, depth-1 LDG pipeline,
// re-zeros the consumed hist region at the end.
#define SEGS_PER_WARP 8

struct C4 { float4 a, b, c, d; };     // one segment's 16 count slots

static __device__ __forceinline__ C4 load_counts(int t) {
    const float4* p = reinterpret_cast<const float4*>(g_hist) + (t << 2);
    C4 r; r.a = p[0]; r.b = p[1]; r.c = p[2]; r.d = p[3];
    return r;
}

static __device__ __forceinline__ void process_seg(
    const C4& h, const unsigned long long* e01, const unsigned long long* e23,
    float4* __restrict__ out, int t, int lane)
{
    float len = (((h.a.x + h.a.y) + (h.a.z + h.a.w))
              +  ((h.b.x + h.b.y) + (h.b.z + h.b.w)))
              + (((h.c.x + h.c.y) + (h.c.z + h.c.w))
              +  (h.d.x + h.d.y));
    float scale = __fdividef(1.0f, fmaxf(len, 1.0f));   // empty seg -> 0 out

    const float cv[14] = { h.a.x, h.a.y, h.a.z, h.a.w,
                           h.b.x, h.b.y, h.b.z, h.b.w,
                           h.c.x, h.c.y, h.c.z, h.c.w,
                           h.d.x, h.d.y };

    unsigned long long a01 = 0ull, a23 = 0ull;
#pragma unroll
    for (int v = 0; v < 14; ++v) {
        unsigned long long cc;
        unsigned cb = __float_as_uint(cv[v]);
        asm("mov.b64 %0, {%1, %1};" : "=l"(cc) : "r"(cb));
        asm("fma.rn.f32x2 %0, %1, %2, %0;" : "+l"(a01) : "l"(cc), "l"(e01[v]));
        asm("fma.rn.f32x2 %0, %1, %2, %0;" : "+l"(a23) : "l"(cc), "l"(e23[v]));
    }
    unsigned long long ss;
    unsigned sb = __float_as_uint(scale);
    asm("mov.b64 %0, {%1, %1};" : "=l"(ss) : "r"(sb));
    asm("mul.rn.f32x2 %0, %0, %1;" : "+l"(a01) : "l"(ss));
    asm("mul.rn.f32x2 %0, %0, %1;" : "+l"(a23) : "l"(ss));

    float4 r;
    asm("mov.b64 {%0, %1}, %2;" : "=f"(r.x), "=f"(r.y) : "l"(a01));
    asm("mov.b64 {%0, %1}, %2;" : "=f"(r.z), "=f"(r.w) : "l"(a23));
    out[t * 32 + lane] = r;
}

__global__ void matvec_kernel(const float* __restrict__ emb,
                              float* __restrict__ out, int T) {
    const int lane = threadIdx.x & 31;
    const int warp = threadIdx.x >> 5;
    const int warps_per_block = blockDim.x >> 5;
    const int t0 = (blockIdx.x * warps_per_block + warp) * SEGS_PER_WARP;
    if (t0 >= T) return;

    // Register-resident per-lane slice of the 14x128 table, as f32x2 pairs.
    unsigned long long e01[14], e23[14];
#pragma unroll
    for (int v = 0; v < 14; ++v) {
        float4 e = *reinterpret_cast<const float4*>(emb + v * 128 + lane * 4);
        asm("mov.b64 %0, {%1, %2};" : "=l"(e01[v])
            : "r"(__float_as_uint(e.x)), "r"(__float_as_uint(e.y)));
        asm("mov.b64 %0, {%1, %2};" : "=l"(e23[v])
            : "r"(__float_as_uint(e.z)), "r"(__float_as_uint(e.w)));
    }

    float4* out4 = reinterpret_cast<float4*>(out);

    if (t0 + SEGS_PER_WARP <= T) {       // fast path: full 8-segment chunk
        C4 cur = load_counts(t0);
#pragma unroll
        for (int s = 0; s < SEGS_PER_WARP; ++s) {
            C4 nxt;
            if (s + 1 < SEGS_PER_WARP) nxt = load_counts(t0 + s + 1);
            process_seg(cur, e01, e23, out4, t0 + s, lane);
            cur = nxt;
        }
        // Re-zero the 8*64B hist region just consumed: 32 lanes x 16B.
        reinterpret_cast<float4*>(g_hist)[(t0 << 2) + lane] =
            make_float4(0.f, 0.f, 0.f, 0.f);
    } else {                              // tail chunk
        for (int s = 0; s < SEGS_PER_WARP; ++s) {
            int t = t0 + s;
            if (t >= T) break;
            C4 cur = load_counts(t);
            process_seg(cur, e01, e23, out4, t, lane);
            if (lane < 4)
                reinterpret_cast<float4*>(g_hist)[(t << 2) + lane] =
                    make_float4(0.f, 0.f, 0.f, 0.f);
        }
    }
}

// ---------------------------------------------------------------------------
extern "C" void kernel_launch(void* const* d_in, const int* in_sizes, int n_in,
                              void* d_out, int out_size) {
    const float* char_emb     = (const float*)d_in[0];
    const int*   char_indices = (const int*)d_in[1];
    const int*   segment_ids  = (const int*)d_in[2];
    float*       out          = (float*)d_out;

    int N = in_sizes[1];          // total chars
    int T = out_size / 128;       // segments (d_model = 128)

    {   // histogram: 4 chars/thread (+1 thread for the tail)
        int nq = N >> 2;
        int threads = 256;
        int work = nq + 1;
        hist_kernel<<<(work + threads - 1) / threads, threads>>>(
            (const int4*)segment_ids, (const int4*)char_indices,
            segment_ids, char_indices, nq, N);
    }
    {   // matvec: 8 warps/block, 8 segments/warp -> 64 segments/block
        int threads = 256;
        int segs_per_block = (threads / 32) * SEGS_PER_WARP;
        int blocks = (T + segs_per_block - 1) / segs_per_block;
        matvec_kernel<<<blocks, threads>>>(char_emb, out, T);
    }
}

// round 5
// speedup vs baseline: 2.8725x; 1.2373x over previous
#include <cuda_runtime.h>
#include <cuda_bf16.h>
#include <cstdint>

// Per-segment vocab histogram, f32, 16 slots (64B)/segment. Slots 14,15 never
// written. Zero-initialized at module load; the mma kernel re-zeros rows it
// consumes, so every graph replay starts from zeros.
#define MAX_T_ (1 << 17)
__device__ float g_hist[MAX_T_ * 16];

// pack two f32 -> bf16x2 ('lo' lands in the low 16 bits)
#define PACK_BF16X2(res, lo, hi) \
    asm("cvt.rn.bf16x2.f32 %0, %1, %2;" : "=r"(res) : "f"(hi), "f"(lo))

static __device__ __forceinline__ void mma_bf16(
    float& d0, float& d1, float& d2, float& d3,
    uint32_t a0, uint32_t a1, uint32_t a2, uint32_t a3,
    uint32_t b0, uint32_t b1)
{
    asm volatile(
        "mma.sync.aligned.m16n8k16.row.col.f32.bf16.bf16.f32 "
        "{%0,%1,%2,%3}, {%4,%5,%6,%7}, {%8,%9}, {%0,%1,%2,%3};"
        : "+f"(d0), "+f"(d1), "+f"(d2), "+f"(d3)
        : "r"(a0), "r"(a1), "r"(a2), "r"(a3), "r"(b0), "r"(b1));
}

// ---------------------------------------------------------------------------
// Kernel 1: histogram, 4 chars/thread via int4 loads, f32 RED.ADD.
__global__ void hist_kernel(const int4* __restrict__ seg4,
                            const int4* __restrict__ cidx4,
                            const int* __restrict__ seg,
                            const int* __restrict__ cidx,
                            int nq, int N) {
    int i = blockIdx.x * blockDim.x + threadIdx.x;
    if (i < nq) {
        int4 s = seg4[i];
        int4 c = cidx4[i];
        atomicAdd(&g_hist[(s.x << 4) + c.x], 1.0f);
        atomicAdd(&g_hist[(s.y << 4) + c.y], 1.0f);
        atomicAdd(&g_hist[(s.z << 4) + c.z], 1.0f);
        atomicAdd(&g_hist[(s.w << 4) + c.w], 1.0f);
    } else if (i == nq) {
        for (int j = nq * 4; j < N; ++j)
            atomicAdd(&g_hist[(seg[j] << 4) + cidx[j]], 1.0f);
    }
}

// ---------------------------------------------------------------------------
// Kernel 2: warp-level bf16 HMMA GEMM.
//   out[t][n] = (sum_v hist[t][v] * emb[v][n]) / max(len_t, 1)
//   A (16x16 per m-tile): counts, straight from hist -> bf16 (exact).
//   B (16x8 per n-tile):  emb split hi+lo (two accumulating MMAs), rows 14,15
//                         zero-padded. Precomputed once per warp (64 regs).
// Each warp processes WTILES m-tiles of 16 segments = 64 segments.
#define WTILES 4

__global__ void __launch_bounds__(256)
mma_kernel(const float* __restrict__ emb, float* __restrict__ out, int T) {
    const int lane = threadIdx.x & 31;
    const int q = lane & 3;         // threadID_in_group
    const int g = lane >> 2;        // groupID
    const int warp_id = blockIdx.x * 8 + (threadIdx.x >> 5);
    const int t_base = warp_id * (WTILES * 16);
    if (t_base >= T) return;

    // ---- B fragments: bhi/blo[j] covers output cols 8j..8j+7 ----
    // b0 rows k = 2q,2q+1 ; b1 rows k = 2q+8,2q+9 ; col n = 8j+g.
    uint32_t bhi[16][2], blo[16][2];
    const int k0 = 2 * q, k1 = 2 * q + 1, k2 = 2 * q + 8, k3 = 2 * q + 9;
#pragma unroll
    for (int j = 0; j < 16; ++j) {
        const int n = 8 * j + g;
        float e0 = (k0 < 14) ? emb[k0 * 128 + n] : 0.f;
        float e1 = (k1 < 14) ? emb[k1 * 128 + n] : 0.f;
        float e2 = (k2 < 14) ? emb[k2 * 128 + n] : 0.f;
        float e3 = (k3 < 14) ? emb[k3 * 128 + n] : 0.f;
        uint32_t h0, h1;
        PACK_BF16X2(h0, e0, e1);
        PACK_BF16X2(h1, e2, e3);
        bhi[j][0] = h0; bhi[j][1] = h1;
        float r0 = e0 - __uint_as_float(h0 << 16);
        float r1 = e1 - __uint_as_float(h0 & 0xffff0000u);
        float r2 = e2 - __uint_as_float(h1 << 16);
        float r3 = e3 - __uint_as_float(h1 & 0xffff0000u);
        uint32_t l0, l1;
        PACK_BF16X2(l0, r0, r1);
        PACK_BF16X2(l1, r2, r3);
        blo[j][0] = l0; blo[j][1] = l1;
    }

    const float2* hist2 = reinterpret_cast<const float2*>(g_hist);
    const float4  zero4 = make_float4(0.f, 0.f, 0.f, 0.f);

    for (int mt = 0; mt < WTILES; ++mt) {
        const int t0 = t_base + mt * 16;
        if (t0 >= T) return;
        const int tr0 = t0 + g;          // rows this lane owns
        const int tr1 = t0 + g + 8;
        const bool ok0 = (tr0 < T);
        const bool ok1 = (tr1 < T);

        // ---- A fragments + segment lengths (hist row stride = 8 float2) ----
        float2 p00 = make_float2(0.f, 0.f), p01 = p00, p10 = p00, p11 = p00;
        if (ok0) { p00 = hist2[(size_t)tr0 * 8 + q];
                   p01 = hist2[(size_t)tr0 * 8 + q + 4]; }
        if (ok1) { p10 = hist2[(size_t)tr1 * 8 + q];
                   p11 = hist2[(size_t)tr1 * 8 + q + 4]; }

        uint32_t a0, a1, a2, a3;
        PACK_BF16X2(a0, p00.x, p00.y);
        PACK_BF16X2(a1, p10.x, p10.y);
        PACK_BF16X2(a2, p01.x, p01.y);
        PACK_BF16X2(a3, p11.x, p11.y);

        float len0 = (p00.x + p00.y) + (p01.x + p01.y);
        float len1 = (p10.x + p10.y) + (p11.x + p11.y);
        len0 += __shfl_xor_sync(0xffffffffu, len0, 1);
        len1 += __shfl_xor_sync(0xffffffffu, len1, 1);
        len0 += __shfl_xor_sync(0xffffffffu, len0, 2);
        len1 += __shfl_xor_sync(0xffffffffu, len1, 2);
        const float s0 = __fdividef(1.0f, fmaxf(len0, 1.0f));
        const float s1 = __fdividef(1.0f, fmaxf(len1, 1.0f));

        // ---- consume-and-clear hist rows t0..t0+15 (this warp only) ----
        {
            const int zr = t0 + (lane >> 1);
            if (zr < T) {
                float4* hz = reinterpret_cast<float4*>(
                    g_hist + (size_t)zr * 16 + (lane & 1) * 8);
                hz[0] = zero4; hz[1] = zero4;
            }
        }

        // ---- 16 n-tiles: 2 MMAs (hi, lo) + scaled stores ----
        float* po0 = out + (size_t)tr0 * 128 + 2 * q;
        float* po1 = out + (size_t)tr1 * 128 + 2 * q;
#pragma unroll
        for (int j = 0; j < 16; ++j) {
            float d0 = 0.f, d1 = 0.f, d2 = 0.f, d3 = 0.f;
            mma_bf16(d0, d1, d2, d3, a0, a1, a2, a3, bhi[j][0], bhi[j][1]);
            mma_bf16(d0, d1, d2, d3, a0, a1, a2, a3, blo[j][0], blo[j][1]);
            if (ok0) *reinterpret_cast<float2*>(po0 + 8 * j) =
                         make_float2(d0 * s0, d1 * s0);
            if (ok1) *reinterpret_cast<float2*>(po1 + 8 * j) =
                         make_float2(d2 * s1, d3 * s1);
        }
    }
}

// ---------------------------------------------------------------------------
extern "C" void kernel_launch(void* const* d_in, const int* in_sizes, int n_in,
                              void* d_out, int out_size) {
    const float* char_emb     = (const float*)d_in[0];
    const int*   char_indices = (const int*)d_in[1];
    const int*   segment_ids  = (const int*)d_in[2];
    float*       out          = (float*)d_out;

    int N = in_sizes[1];          // total chars
    int T = out_size / 128;       // segments (d_model = 128)

    {   // histogram
        int nq = N >> 2;
        int threads = 256;
        int work = nq + 1;
        hist_kernel<<<(work + threads - 1) / threads, threads>>>(
            (const int4*)segment_ids, (const int4*)char_indices,
            segment_ids, char_indices, nq, N);
    }
    {   // HMMA GEMM: 8 warps/block, 64 segments/warp -> 512 segments/block
        int segs_per_block = 8 * WTILES * 16;
        int blocks = (T + segs_per_block - 1) / segs_per_block;
        mma_kernel<<<blocks, 256>>>(char_emb, out, T);
    }
}

// round 6
// speedup vs baseline: 3.1033x; 1.0804x over previous
#include <cuda_runtime.h>
#include <cuda_bf16.h>
#include <cstdint>

// Per-segment vocab histogram, f32, 16 slots (64B)/segment. Slots 14,15 never
// written. Zero-initialized at module load; the mma kernel re-zeros rows it
// consumes, so every graph replay starts from zeros.
#define MAX_T_ (1 << 17)
__device__ float g_hist[MAX_T_ * 16];

// pack two f32 -> bf16x2 ('lo' lands in the low 16 bits)
#define PACK_BF16X2(res, lo, hi) \
    asm("cvt.rn.bf16x2.f32 %0, %1, %2;" : "=r"(res) : "f"(hi), "f"(lo))

static __device__ __forceinline__ void mma_bf16(
    float& d0, float& d1, float& d2, float& d3,
    uint32_t a0, uint32_t a1, uint32_t a2, uint32_t a3,
    uint32_t b0, uint32_t b1)
{
    asm volatile(
        "mma.sync.aligned.m16n8k16.row.col.f32.bf16.bf16.f32 "
        "{%0,%1,%2,%3}, {%4,%5,%6,%7}, {%8,%9}, {%0,%1,%2,%3};"
        : "+f"(d0), "+f"(d1), "+f"(d2), "+f"(d3)
        : "r"(a0), "r"(a1), "r"(a2), "r"(a3), "r"(b0), "r"(b1));
}

// ---------------------------------------------------------------------------
// Kernel 1: histogram, 4 chars/thread via int4 loads, f32 RED.ADD.
__global__ void hist_kernel(const int4* __restrict__ seg4,
                            const int4* __restrict__ cidx4,
                            const int* __restrict__ seg,
                            const int* __restrict__ cidx,
                            int nq, int N) {
    int i = blockIdx.x * blockDim.x + threadIdx.x;
    if (i < nq) {
        int4 s = seg4[i];
        int4 c = cidx4[i];
        atomicAdd(&g_hist[(s.x << 4) + c.x], 1.0f);
        atomicAdd(&g_hist[(s.y << 4) + c.y], 1.0f);
        atomicAdd(&g_hist[(s.z << 4) + c.z], 1.0f);
        atomicAdd(&g_hist[(s.w << 4) + c.w], 1.0f);
    } else if (i == nq) {
        for (int j = nq * 4; j < N; ++j)
            atomicAdd(&g_hist[(seg[j] << 4) + cidx[j]], 1.0f);
    }
}

// ---------------------------------------------------------------------------
// Kernel 2: warp-pair bf16 HMMA GEMM.
//   out[t][n] = (sum_v hist[t][v] * emb[v][n]) / max(len_t, 1)
// Warps work in pairs over the same 128 segments: even warp -> cols 0..63,
// odd warp -> cols 64..127. B (emb hi+lo bf16 split) is 32 regs per warp.
// Hist loads are software-pipelined one m-tile ahead; hi/lo MMAs use
// independent accumulators. Even warp re-zeros consumed hist rows after a
// pair-scoped named barrier (so the odd warp's loads are complete).
#define WTILES 8   // m-tiles of 16 segments per warp-pair

__global__ void __launch_bounds__(256, 3)
mma_kernel(const float* __restrict__ emb, float* __restrict__ out, int T) {
    const int lane = threadIdx.x & 31;
    const int q    = lane & 3;          // threadID_in_group
    const int g    = lane >> 2;         // groupID
    const int half = (threadIdx.x >> 5) & 1;          // 0: cols 0-63, 1: 64-127
    const int pair_in_blk = threadIdx.x >> 6;         // 0..3
    const int pair = blockIdx.x * 4 + pair_in_blk;
    const int t_base = pair * (WTILES * 16);
    if (t_base >= T) return;
    const int bar_id = 8 + pair_in_blk;               // named barrier per pair

    // ---- B fragments for this half: j covers cols 64*half + 8j .. +7 ----
    uint32_t bhi[8][2], blo[8][2];
    const int k0 = 2 * q, k1 = 2 * q + 1, k2 = 2 * q + 8, k3 = 2 * q + 9;
#pragma unroll
    for (int j = 0; j < 8; ++j) {
        const int n = 64 * half + 8 * j + g;
        float e0 = (k0 < 14) ? emb[k0 * 128 + n] : 0.f;
        float e1 = (k1 < 14) ? emb[k1 * 128 + n] : 0.f;
        float e2 = (k2 < 14) ? emb[k2 * 128 + n] : 0.f;
        float e3 = (k3 < 14) ? emb[k3 * 128 + n] : 0.f;
        uint32_t h0, h1;
        PACK_BF16X2(h0, e0, e1);
        PACK_BF16X2(h1, e2, e3);
        bhi[j][0] = h0; bhi[j][1] = h1;
        float r0 = e0 - __uint_as_float(h0 << 16);
        float r1 = e1 - __uint_as_float(h0 & 0xffff0000u);
        float r2 = e2 - __uint_as_float(h1 << 16);
        float r3 = e3 - __uint_as_float(h1 & 0xffff0000u);
        uint32_t l0, l1;
        PACK_BF16X2(l0, r0, r1);
        PACK_BF16X2(l1, r2, r3);
        blo[j][0] = l0; blo[j][1] = l1;
    }

    const float2* hist2 = reinterpret_cast<const float2*>(g_hist);
    const float4  zero4 = make_float4(0.f, 0.f, 0.f, 0.f);
    const float2  zero2 = make_float2(0.f, 0.f);

    // ---- prologue: load m-tile 0 ----
    int t0 = t_base;
    float2 p00 = zero2, p01 = zero2, p10 = zero2, p11 = zero2;
    {
        const int tr0 = t0 + g, tr1 = t0 + g + 8;
        if (tr0 < T) { p00 = hist2[(size_t)tr0 * 8 + q];
                       p01 = hist2[(size_t)tr0 * 8 + q + 4]; }
        if (tr1 < T) { p10 = hist2[(size_t)tr1 * 8 + q];
                       p11 = hist2[(size_t)tr1 * 8 + q + 4]; }
    }

#pragma unroll 1
    for (int mt = 0; mt < WTILES; ++mt) {
        const int tr0 = t0 + g;
        const int tr1 = t0 + g + 8;
        const bool ok0 = (tr0 < T);
        const bool ok1 = (tr1 < T);

        // ---- pack A fragments + segment lengths (consumes the loads) ----
        uint32_t a0, a1, a2, a3;
        PACK_BF16X2(a0, p00.x, p00.y);
        PACK_BF16X2(a1, p10.x, p10.y);
        PACK_BF16X2(a2, p01.x, p01.y);
        PACK_BF16X2(a3, p11.x, p11.y);

        float len0 = (p00.x + p00.y) + (p01.x + p01.y);
        float len1 = (p10.x + p10.y) + (p11.x + p11.y);
        len0 += __shfl_xor_sync(0xffffffffu, len0, 1);
        len1 += __shfl_xor_sync(0xffffffffu, len1, 1);
        len0 += __shfl_xor_sync(0xffffffffu, len0, 2);
        len1 += __shfl_xor_sync(0xffffffffu, len1, 2);
        const float s0 = __fdividef(1.0f, fmaxf(len0, 1.0f));
        const float s1 = __fdividef(1.0f, fmaxf(len1, 1.0f));

        // ---- pair barrier: both warps' loads of these rows are complete ----
        asm volatile("bar.sync %0, %1;" :: "r"(bar_id), "r"(64) : "memory");

        // ---- even warp clears the consumed rows ----
        if (half == 0) {
            const int zr = t0 + (lane >> 1);
            if (zr < T) {
                float4* hz = reinterpret_cast<float4*>(
                    g_hist + (size_t)zr * 16 + (lane & 1) * 8);
                hz[0] = zero4; hz[1] = zero4;
            }
        }

        // ---- prefetch next m-tile's hist rows ----
        const int t0n = t0 + 16;
        if (mt + 1 < WTILES) {
            const int nr0 = t0n + g, nr1 = t0n + g + 8;
            p00 = zero2; p01 = zero2; p10 = zero2; p11 = zero2;
            if (nr0 < T) { p00 = hist2[(size_t)nr0 * 8 + q];
                           p01 = hist2[(size_t)nr0 * 8 + q + 4]; }
            if (nr1 < T) { p10 = hist2[(size_t)nr1 * 8 + q];
                           p11 = hist2[(size_t)nr1 * 8 + q + 4]; }
        }

        // ---- 8 n-tiles: independent hi/lo MMAs + scaled stores ----
        float* po0 = out + (size_t)tr0 * 128 + 64 * half + 2 * q;
        float* po1 = out + (size_t)tr1 * 128 + 64 * half + 2 * q;
#pragma unroll
        for (int j = 0; j < 8; ++j) {
            float h0 = 0.f, h1 = 0.f, h2 = 0.f, h3 = 0.f;
            float l0 = 0.f, l1 = 0.f, l2 = 0.f, l3 = 0.f;
            mma_bf16(h0, h1, h2, h3, a0, a1, a2, a3, bhi[j][0], bhi[j][1]);
            mma_bf16(l0, l1, l2, l3, a0, a1, a2, a3, blo[j][0], blo[j][1]);
            if (ok0) *reinterpret_cast<float2*>(po0 + 8 * j) =
                         make_float2((h0 + l0) * s0, (h1 + l1) * s0);
            if (ok1) *reinterpret_cast<float2*>(po1 + 8 * j) =
                         make_float2((h2 + l2) * s1, (h3 + l3) * s1);
        }

        t0 = t0n;
    }
}

// ---------------------------------------------------------------------------
extern "C" void kernel_launch(void* const* d_in, const int* in_sizes, int n_in,
                              void* d_out, int out_size) {
    const float* char_emb     = (const float*)d_in[0];
    const int*   char_indices = (const int*)d_in[1];
    const int*   segment_ids  = (const int*)d_in[2];
    float*       out          = (float*)d_out;

    int N = in_sizes[1];          // total chars
    int T = out_size / 128;       // segments (d_model = 128)

    {   // histogram
        int nq = N >> 2;
        int threads = 256;
        int work = nq + 1;
        hist_kernel<<<(work + threads - 1) / threads, threads>>>(
            (const int4*)segment_ids, (const int4*)char_indices,
            segment_ids, char_indices, nq, N);
    }
    {   // HMMA GEMM: 8 warps = 4 warp-pairs per block, 128 segs per pair
        int segs_per_block = 4 * WTILES * 16;
        int blocks = (T + segs_per_block - 1) / segs_per_block;
        mma_kernel<<<blocks, 256>>>(char_emb, out, T);
    }
}